// round 1
// baseline (speedup 1.0000x reference)
#include <cuda_runtime.h>

// ---------------------------------------------------------------------------
// TrackCrop: input [32, 512, 512, 3] f32.
// Per batch: count nonzeros, coordinate-weighted sums -> centroid -> clamped
// 256x256 crop top-left corner -> gather crop.
// ---------------------------------------------------------------------------

#define NBATCH 32
#define SY 512
#define SX 512
#define NC 3
#define ROW_FLOATS (SX * NC)        // 1536 floats per row
#define ROW_F4 (ROW_FLOATS / 4)     // 384 float4 per row
#define CROP 256
#define OUT_ROW_FLOATS (CROP * NC)  // 768

__device__ int g_cnt[NBATCH];
__device__ int g_sx[NBATCH];
__device__ int g_sy[NBATCH];

__global__ void zero_scratch_kernel() {
    int t = threadIdx.x;
    if (t < NBATCH) {
        g_cnt[t] = 0;
        g_sx[t]  = 0;
        g_sy[t]  = 0;
    }
}

// One block (128 threads) per image row. Reduces per-row nonzero count and
// x-weighted sum; sy contribution is y * row_count.
__global__ __launch_bounds__(128) void reduce_kernel(const float* __restrict__ in) {
    const int y = blockIdx.x;   // 0..511
    const int b = blockIdx.y;   // 0..31
    const int t = threadIdx.x;  // 0..127

    const float4* __restrict__ row =
        (const float4*)(in + ((size_t)b * SY + y) * ROW_FLOATS);

    int cnt = 0;
    int sx  = 0;
    #pragma unroll
    for (int i = 0; i < 3; i++) {
        const int q = t + i * 128;      // float4 index within row, < 384
        const float4 v = row[q];
        const int j = 4 * q;            // float index within row
        if (v.x != 0.0f) { cnt++; sx += (j    ) / 3; }
        if (v.y != 0.0f) { cnt++; sx += (j + 1) / 3; }
        if (v.z != 0.0f) { cnt++; sx += (j + 2) / 3; }
        if (v.w != 0.0f) { cnt++; sx += (j + 3) / 3; }
    }

    // warp reduce
    #pragma unroll
    for (int o = 16; o > 0; o >>= 1) {
        cnt += __shfl_down_sync(0xFFFFFFFFu, cnt, o);
        sx  += __shfl_down_sync(0xFFFFFFFFu, sx,  o);
    }

    __shared__ int s_cnt, s_sx;
    if (t == 0) { s_cnt = 0; s_sx = 0; }
    __syncthreads();
    if ((t & 31) == 0) {
        atomicAdd(&s_cnt, cnt);
        atomicAdd(&s_sx,  sx);
    }
    __syncthreads();
    if (t == 0) {
        atomicAdd(&g_cnt[b], s_cnt);
        atomicAdd(&g_sx[b],  s_sx);
        atomicAdd(&g_sy[b],  y * s_cnt);
    }
}

// One block (192 threads) per output row. Thread 0 recomputes the crop origin
// exactly as the reference does (int32 -> f32 RN, IEEE f32 divide, truncating
// cast to int32), then each thread copies 4 floats (aligned float4 store).
__global__ __launch_bounds__(192) void crop_kernel(const float* __restrict__ in,
                                                   float* __restrict__ out) {
    const int r = blockIdx.x;   // output row 0..255
    const int b = blockIdx.y;   // batch
    const int t = threadIdx.x;  // 0..191

    __shared__ int sH, sW;
    if (t == 0) {
        const float fc = __int2float_rn(g_cnt[b]);
        const int xc = (int)__fdiv_rn(__int2float_rn(g_sx[b]), fc);
        const int yc = (int)__fdiv_rn(__int2float_rn(g_sy[b]), fc);
        // clamp: min(max(c - 128, 0), 512 - 1 - 256) = [0, 255]
        sH = min(max(yc - CROP / 2, 0), SY - 1 - CROP);
        sW = min(max(xc - CROP / 2, 0), SX - 1 - CROP);
    }
    __syncthreads();

    const float* __restrict__ src =
        in + (size_t)b * (SY * SX * NC)
           + ((size_t)(sH + r) * SX + sW) * NC
           + 4 * t;
    float4* __restrict__ dst =
        (float4*)(out + ((size_t)b * CROP + r) * OUT_ROW_FLOATS) + t;

    float4 v;
    v.x = src[0];
    v.y = src[1];
    v.z = src[2];
    v.w = src[3];
    *dst = v;
}

extern "C" void kernel_launch(void* const* d_in, const int* in_sizes, int n_in,
                              void* d_out, int out_size) {
    const float* in = (const float*)d_in[0];
    float* out = (float*)d_out;

    zero_scratch_kernel<<<1, 32>>>();
    reduce_kernel<<<dim3(SY, NBATCH), 128>>>(in);
    crop_kernel<<<dim3(CROP, NBATCH), 192>>>(in, out);
}